// round 3
// baseline (speedup 1.0000x reference)
#include <cuda_runtime.h>
#include <cuda_fp16.h>

#define BB   2048
#define SS   168
#define FF   7
#define HH   128
#define GG4  512
#define PP   96
#define AAT  135
#define BT   16
#define NCTA 128
#define NTHR 256
#define KB   8
#define WPAD 12
#define HSTR 136
#define WSTR 140

#define OFF_H    0
#define OFF_C    2176
#define OFF_Y    4352
#define OFF_WBUF 4480
#define OFF_BENC 16768
#define OFF_BDEC 17280
#define OFF_BATT 17792
#define OFF_WOUT 17968
#define OFF_WFIN 18864
#define OFF_BOUT 18872
#define OFF_BFIN 18880
#define OFF_U    18896
#define XBS_OFF  OFF_U
#define WIH_OFF  (OFF_U + 18816)
#define WATT_OFF OFF_U
#define SCOR_OFF (OFF_U + SS * WSTR)
#define SMEM_FLOATS (OFF_U + SS * WSTR + BT * SS)
#define SMEM_BYTES  (SMEM_FLOATS * 4)

__device__ __half g_enc[(size_t)BB * SS * HH];

__device__ __forceinline__ unsigned long long pack2(float lo, float hi) {
    unsigned long long r;
    asm("mov.b64 %0, {%1, %2};" : "=l"(r) : "f"(lo), "f"(hi));
    return r;
}
__device__ __forceinline__ void unpack2(unsigned long long v, float &lo, float &hi) {
    asm("mov.b64 {%0, %1}, %2;" : "=f"(lo), "=f"(hi) : "l"(v));
}
__device__ __forceinline__ void fma2(unsigned long long &d, unsigned long long a, unsigned long long b) {
    asm("fma.rn.f32x2 %0, %1, %2, %0;" : "+l"(d) : "l"(a), "l"(b));
}
__device__ __forceinline__ float sigf(float x) { return __fdividef(1.f, 1.f + __expf(-x)); }
__device__ __forceinline__ float tanh_f(float x) {
    float ax = fabsf(x);
    float t  = __expf(-2.f * ax);
    return copysignf(__fdividef(1.f - t, 1.f + t), x);
}

// acc[b16][GR] += A[b16][128] @ W[GR][128]^T, batch pairs packed in f32x2.
// gg = tid>>2 (0..63), bg = tid&3. Thread owns gates gg+64*gi.
template<int NGI, int GR>
__device__ __forceinline__ void gemm_accum(const float* __restrict__ Wg,
                                           const float* __restrict__ As,
                                           unsigned long long (*acc)[2],
                                           float* __restrict__ wbuf,
                                           int tid, int gg, int bg)
{
    constexpr int NC = HH / KB;
    constexpr int NL = GR / 128;
    float4 st[4];
    #pragma unroll
    for (int q = 0; q < NL; ++q) {
        int i = tid + NTHR * q; int g = i >> 1, kq = i & 1;
        st[q] = *(const float4*)(Wg + g * HH + kq * 4);
    }
    #pragma unroll
    for (int q = 0; q < NL; ++q) {
        int i = tid + NTHR * q; int g = i >> 1, kq = i & 1;
        *(float4*)(wbuf + g * WPAD + kq * 4) = st[q];
    }
    __syncthreads();

    #pragma unroll 2
    for (int c = 0; c < NC; ++c) {
        if (c + 1 < NC) {
            #pragma unroll
            for (int q = 0; q < NL; ++q) {
                int i = tid + NTHR * q; int g = i >> 1, kq = i & 1;
                st[q] = *(const float4*)(Wg + g * HH + (c + 1) * KB + kq * 4);
            }
        }
        const float* wb = wbuf + (c & 1) * (GG4 * WPAD);
        const int k0 = c * KB;
        #pragma unroll
        for (int kk = 0; kk < KB; kk += 4) {
            float4 hv0 = *(const float4*)(As + (bg     ) * HSTR + k0 + kk);
            float4 hv1 = *(const float4*)(As + (bg + 4 ) * HSTR + k0 + kk);
            float4 hv2 = *(const float4*)(As + (bg + 8 ) * HSTR + k0 + kk);
            float4 hv3 = *(const float4*)(As + (bg + 12) * HSTR + k0 + kk);
            unsigned long long hp0[4], hp1[4];
            hp0[0] = pack2(hv0.x, hv1.x); hp0[1] = pack2(hv0.y, hv1.y);
            hp0[2] = pack2(hv0.z, hv1.z); hp0[3] = pack2(hv0.w, hv1.w);
            hp1[0] = pack2(hv2.x, hv3.x); hp1[1] = pack2(hv2.y, hv3.y);
            hp1[2] = pack2(hv2.z, hv3.z); hp1[3] = pack2(hv2.w, hv3.w);
            #pragma unroll
            for (int gi = 0; gi < NGI; ++gi) {
                float4 wv = *(const float4*)(wb + (gg + 64 * gi) * WPAD + kk);
                unsigned long long w0 = pack2(wv.x, wv.x);
                unsigned long long w1 = pack2(wv.y, wv.y);
                unsigned long long w2 = pack2(wv.z, wv.z);
                unsigned long long w3 = pack2(wv.w, wv.w);
                fma2(acc[gi][0], w0, hp0[0]); fma2(acc[gi][1], w0, hp1[0]);
                fma2(acc[gi][0], w1, hp0[1]); fma2(acc[gi][1], w1, hp1[1]);
                fma2(acc[gi][0], w2, hp0[2]); fma2(acc[gi][1], w2, hp1[2]);
                fma2(acc[gi][0], w3, hp0[3]); fma2(acc[gi][1], w3, hp1[3]);
            }
        }
        if (c + 1 < NC) {
            float* wbn = wbuf + ((c + 1) & 1) * (GG4 * WPAD);
            #pragma unroll
            for (int q = 0; q < NL; ++q) {
                int i = tid + NTHR * q; int g = i >> 1, kq = i & 1;
                *(float4*)(wbn + g * WPAD + kq * 4) = st[q];
            }
        }
        __syncthreads();
    }
}

extern "C" __global__ void __launch_bounds__(NTHR, 1)
edk_kernel(const float* __restrict__ xb,
           const float* __restrict__ Wih_e, const float* __restrict__ Whh_e,
           const float* __restrict__ bih_e, const float* __restrict__ bhh_e,
           const float* __restrict__ Watt,  const float* __restrict__ batt,
           const float* __restrict__ Wih_d, const float* __restrict__ Whh_d,
           const float* __restrict__ bih_d, const float* __restrict__ bhh_d,
           const float* __restrict__ Wout,  const float* __restrict__ bout,
           const float* __restrict__ Wfin,  const float* __restrict__ bfin,
           float* __restrict__ out)
{
    extern __shared__ float sm[];
    const int tid = threadIdx.x;
    const int gg  = tid >> 2;
    const int bg  = tid & 3;
    const int b0  = blockIdx.x * BT;

    float* h_s    = sm + OFF_H;
    float* c_s    = sm + OFF_C;     // encoder: c;  decoder: combine
    float* y_s    = sm + OFF_Y;
    float* wbuf   = sm + OFF_WBUF;
    float* benc_s = sm + OFF_BENC;
    float* bdec_s = sm + OFF_BDEC;
    float* batt_s = sm + OFF_BATT;
    float* wout_s = sm + OFF_WOUT;
    float* wfin_s = sm + OFF_WFIN;
    float* bout_s = sm + OFF_BOUT;
    float* bfin_s = sm + OFF_BFIN;
    float* xbs    = sm + XBS_OFF;
    float* wih_s  = sm + WIH_OFF;
    float* watt_s = sm + WATT_OFF;
    float* scor_s = sm + SCOR_OFF;

    for (int i = tid; i < BT * SS * FF; i += NTHR) {
        int b = i / (SS * FF), r = i % (SS * FF);
        xbs[b * 1176 + r] = xb[(size_t)(b0 + b) * (SS * FF) + r];
    }
    for (int i = tid; i < GG4; i += NTHR) {
        benc_s[i] = bih_e[i] + bhh_e[i];
        bdec_s[i] = bih_d[i] + bhh_d[i];
    }
    for (int i = tid; i < GG4 * FF; i += NTHR) {
        int g = i / FF, f = i % FF;
        wih_s[g * 8 + f] = Wih_e[i];
    }
    for (int i = tid; i < GG4; i += NTHR) wih_s[i * 8 + 7] = 0.f;
    for (int i = tid; i < BT * HSTR; i += NTHR) { h_s[i] = 0.f; c_s[i] = 0.f; }
    for (int i = tid; i < SS; i += NTHR) batt_s[i] = batt[i];
    for (int i = tid; i < FF * HH; i += NTHR) wout_s[i] = Wout[i];
    if (tid < FF) { wfin_s[tid] = Wfin[tid]; bout_s[tid] = bout[tid]; }
    if (tid == 0) bfin_s[0] = bfin[0];
    __syncthreads();

    // -------- encoder: 168 LSTM steps --------
    for (int s = 0; s < SS; ++s) {
        float af[8][4];
        #pragma unroll
        for (int gi = 0; gi < 8; ++gi) {
            float bb = benc_s[gg + 64 * gi];
            #pragma unroll
            for (int bi = 0; bi < 4; ++bi) af[gi][bi] = bb;
        }
        #pragma unroll
        for (int f = 0; f < FF; ++f) {
            float xv[4];
            #pragma unroll
            for (int bi = 0; bi < 4; ++bi)
                xv[bi] = xbs[(bg + 4 * bi) * 1176 + s * FF + f];
            #pragma unroll
            for (int gi = 0; gi < 8; ++gi) {
                float wv = wih_s[(gg + 64 * gi) * 8 + f];
                #pragma unroll
                for (int bi = 0; bi < 4; ++bi) af[gi][bi] += wv * xv[bi];
            }
        }
        unsigned long long acc[8][2];
        #pragma unroll
        for (int gi = 0; gi < 8; ++gi) {
            acc[gi][0] = pack2(af[gi][0], af[gi][1]);
            acc[gi][1] = pack2(af[gi][2], af[gi][3]);
        }

        gemm_accum<8, GG4>(Whh_e, h_s, acc, wbuf, tid, gg, bg);

        #pragma unroll
        for (int gi = 0; gi < 8; ++gi) {
            unpack2(acc[gi][0], af[gi][0], af[gi][1]);
            unpack2(acc[gi][1], af[gi][2], af[gi][3]);
        }
        #pragma unroll
        for (int jj = 0; jj < 2; ++jj) {
            int j = gg + 64 * jj;
            #pragma unroll
            for (int bi = 0; bi < 4; ++bi) {
                int b = bg + 4 * bi;
                float iv = sigf(af[0 + jj][bi]);
                float fv = sigf(af[2 + jj][bi]);
                float gv = tanh_f(af[4 + jj][bi]);
                float ov = sigf(af[6 + jj][bi]);
                float cc = fv * c_s[b * HSTR + j] + iv * gv;
                float hh = ov * tanh_f(cc);
                c_s[b * HSTR + j] = cc;
                h_s[b * HSTR + j] = hh;
                g_enc[(((size_t)(b0 + b)) * SS + s) * HH + j] = __float2half_rn(hh);
            }
        }
        __syncthreads();
    }

    // y0 = xb[:, -1, :], then overwrite union with W_att
    for (int i = tid; i < BT * 8; i += NTHR) {
        int b = i >> 3, f = i & 7;
        y_s[i] = (f < FF) ? xbs[b * 1176 + (SS - 1) * FF + f] : 0.f;
    }
    __syncthreads();
    for (int i = tid; i < SS * WSTR; i += NTHR) {
        int s_ = i / WSTR, a_ = i % WSTR;
        watt_s[i] = (a_ < AAT) ? Watt[s_ * AAT + a_] : 0.f;
    }
    __syncthreads();

    // -------- decoder: 96 steps --------
    for (int p = 0; p < PP; ++p) {
        // 1) scores = [prev_h | y_prev] @ W_att^T + b_att
        {
            int b = tid >> 4, ts = tid & 15;
            float acs[11];
            #pragma unroll
            for (int si = 0; si < 11; ++si) acs[si] = 0.f;
            #pragma unroll 2
            for (int a4 = 0; a4 < 34; ++a4) {
                float4 av;
                if (a4 < 32) av = *(const float4*)(h_s + b * HSTR + a4 * 4);
                else         av = *(const float4*)(y_s + b * 8 + (a4 - 32) * 4);
                #pragma unroll
                for (int si = 0; si < 11; ++si) {
                    int s_ = ts + 16 * si;
                    if (s_ < SS) {
                        float4 wv = *(const float4*)(watt_s + s_ * WSTR + a4 * 4);
                        acs[si] += av.x * wv.x + av.y * wv.y + av.z * wv.z + av.w * wv.w;
                    }
                }
            }
            #pragma unroll
            for (int si = 0; si < 11; ++si) {
                int s_ = ts + 16 * si;
                if (s_ < SS) scor_s[b * SS + s_] = acs[si] + batt_s[s_];
            }
        }
        __syncthreads();

        // 2) softmax (warp = 2 rows, 16-lane halves)
        {
            int w = tid >> 5, lane = tid & 31;
            int b = 2 * w + (lane >> 4), l = lane & 15;
            float mx = -1e30f;
            for (int s_ = l; s_ < SS; s_ += 16) mx = fmaxf(mx, scor_s[b * SS + s_]);
            #pragma unroll
            for (int o = 8; o >= 1; o >>= 1) mx = fmaxf(mx, __shfl_xor_sync(0xffffffffu, mx, o));
            float sum = 0.f;
            for (int s_ = l; s_ < SS; s_ += 16) {
                float e = __expf(scor_s[b * SS + s_] - mx);
                scor_s[b * SS + s_] = e;
                sum += e;
            }
            #pragma unroll
            for (int o = 8; o >= 1; o >>= 1) sum += __shfl_xor_sync(0xffffffffu, sum, o);
            float inv = __fdividef(1.f, sum);
            for (int s_ = l; s_ < SS; s_ += 16) scor_s[b * SS + s_] *= inv;
        }
        __syncthreads();

        // 3) combine = attn_w @ enc_out  (fp16 L2-resident reads)
        {
            int b = tid >> 4, hq = tid & 15;
            const __half* ep = g_enc + (((size_t)(b0 + b)) * SS) * HH + hq * 8;
            float acm[8];
            #pragma unroll
            for (int q = 0; q < 8; ++q) acm[q] = 0.f;
            #pragma unroll 8
            for (int s_ = 0; s_ < SS; ++s_) {
                float w = scor_s[b * SS + s_];
                uint4 v = *(const uint4*)(ep + (size_t)s_ * HH);
                __half2* hp = (__half2*)&v;
                #pragma unroll
                for (int q = 0; q < 4; ++q) {
                    float2 f2 = __half22float2(hp[q]);
                    acm[2 * q]     += w * f2.x;
                    acm[2 * q + 1] += w * f2.y;
                }
            }
            #pragma unroll
            for (int q = 0; q < 8; ++q) c_s[b * HSTR + hq * 8 + q] = acm[q];
        }
        __syncthreads();

        // 4) gates (i/f/g only -> first 384 rows of W)
        float af[6][4];
        {
            unsigned long long acc[6][2];
            #pragma unroll
            for (int gi = 0; gi < 6; ++gi) {
                float bb = bdec_s[gg + 64 * gi];
                acc[gi][0] = pack2(bb, bb);
                acc[gi][1] = pack2(bb, bb);
            }
            gemm_accum<6, 384>(Wih_d, c_s, acc, wbuf, tid, gg, bg);
            gemm_accum<6, 384>(Whh_d, h_s, acc, wbuf, tid, gg, bg);
            #pragma unroll
            for (int gi = 0; gi < 6; ++gi) {
                unpack2(acc[gi][0], af[gi][0], af[gi][1]);
                unpack2(acc[gi][1], af[gi][2], af[gi][3]);
            }
        }

        // 5) c_new = sig(f)*prev_h + sig(i)*tanh(g); carry h := c_new
        #pragma unroll
        for (int jj = 0; jj < 2; ++jj) {
            int j = gg + 64 * jj;
            #pragma unroll
            for (int bi = 0; bi < 4; ++bi) {
                int b = bg + 4 * bi;
                float iv = sigf(af[0 + jj][bi]);
                float fv = sigf(af[2 + jj][bi]);
                float gv = tanh_f(af[4 + jj][bi]);
                h_s[b * HSTR + j] = fv * h_s[b * HSTR + j] + iv * gv;
            }
        }
        __syncthreads();

        // 6) out = c_new @ W_out^T + b_out; final = out @ W_fin + b_fin
        if (tid < BT * FF) {
            int b = tid / FF, f = tid % FF;
            float a = 0.f;
            #pragma unroll
            for (int j4 = 0; j4 < 32; ++j4) {
                float4 cv = *(const float4*)(h_s + b * HSTR + j4 * 4);
                float4 wv = *(const float4*)(wout_s + f * HH + j4 * 4);
                a += cv.x * wv.x + cv.y * wv.y + cv.z * wv.z + cv.w * wv.w;
            }
            y_s[b * 8 + f] = a + bout_s[f];
        }
        __syncthreads();
        if (tid < BT) {
            float a = bfin_s[0];
            #pragma unroll
            for (int f = 0; f < FF; ++f) a += y_s[tid * 8 + f] * wfin_s[f];
            out[(size_t)(b0 + tid) * PP + p] = a;
        }
        __syncthreads();
    }
}

extern "C" void kernel_launch(void* const* d_in, const int* in_sizes, int n_in,
                              void* d_out, int out_size)
{
    (void)in_sizes; (void)n_in; (void)out_size;
    cudaFuncSetAttribute(edk_kernel, cudaFuncAttributeMaxDynamicSharedMemorySize, SMEM_BYTES);
    edk_kernel<<<NCTA, NTHR, SMEM_BYTES>>>(
        (const float*)d_in[0],  (const float*)d_in[1],  (const float*)d_in[2],
        (const float*)d_in[3],  (const float*)d_in[4],  (const float*)d_in[5],
        (const float*)d_in[6],  (const float*)d_in[7],  (const float*)d_in[8],
        (const float*)d_in[9],  (const float*)d_in[10], (const float*)d_in[11],
        (const float*)d_in[12], (const float*)d_in[13], (const float*)d_in[14],
        (float*)d_out);
}